// round 4
// baseline (speedup 1.0000x reference)
#include <cuda_runtime.h>
#include <cstdint>

#define BATCH 8
#define NNODES 50000
#define DIM 64
#define ROW_F4 16
#define TOTAL_ROWS ((size_t)BATCH * NNODES)   // 400000

__device__ float4 g_agg[TOTAL_ROWS * ROW_F4];   // 102.4 MB scratch, 16B-aligned
__device__ int g_is64;

// ---------------------------------------------------------------------------
// packed f32x2 helpers
// ---------------------------------------------------------------------------
__device__ __forceinline__ unsigned long long pack2(float a, float b) {
    unsigned long long r;
    asm("mov.b64 %0, {%1, %2};" : "=l"(r) : "f"(a), "f"(b));
    return r;
}
__device__ __forceinline__ unsigned long long fma2(unsigned long long a,
                                                   unsigned long long b,
                                                   unsigned long long c) {
    unsigned long long d;
    asm("fma.rn.f32x2 %0, %1, %2, %3;" : "=l"(d) : "l"(a), "l"(b), "l"(c));
    return d;
}
__device__ __forceinline__ void unpack2(unsigned long long v, float& lo, float& hi) {
    asm("mov.b64 {%0, %1}, %2;" : "=f"(lo), "=f"(hi) : "l"(v));
}

// ---------------------------------------------------------------------------
// Kernel 0: detect edge_index dtype (int64 LE => odd 32-bit words all zero).
// ---------------------------------------------------------------------------
__global__ void detect_dtype_kernel(const int* __restrict__ w, int nwords) {
    __shared__ int any_nonzero;
    if (threadIdx.x == 0) any_nonzero = 0;
    __syncthreads();
    int limit = nwords / 2;
    if (limit > 16384) limit = 16384;
    for (int i = threadIdx.x; i < limit; i += blockDim.x) {
        if (w[2 * i + 1] != 0) any_nonzero = 1;
    }
    __syncthreads();
    if (threadIdx.x == 0) g_is64 = (any_nonzero == 0) ? 1 : 0;
}

// ---------------------------------------------------------------------------
// Kernel 1: zero agg
// ---------------------------------------------------------------------------
__global__ void zero_agg_kernel() {
    const size_t total4 = TOTAL_ROWS * ROW_F4;
    float4 z = make_float4(0.f, 0.f, 0.f, 0.f);
    for (size_t i = (size_t)blockIdx.x * blockDim.x + threadIdx.x;
         i < total4;
         i += (size_t)gridDim.x * blockDim.x) {
        g_agg[i] = z;
    }
}

// ---------------------------------------------------------------------------
// Kernel 2: batch-phased edge scatter (near L2 cap; unchanged from R3)
// ---------------------------------------------------------------------------
__global__ void scatter_kernel(const float* __restrict__ x,
                               const void* __restrict__ edges_raw,
                               int nwords) {
    int is64 = g_is64;
    int num_edges;
    if (is64) {
        num_edges = (nwords >= 3000000) ? (nwords >> 2) : (nwords >> 1);
    } else {
        num_edges = nwords >> 1;
    }

    size_t gtid = (size_t)blockIdx.x * blockDim.x + threadIdx.x;
    int eid = (int)(gtid >> 4);
    int c = (int)(gtid & 15);
    if (eid >= num_edges) return;

    int b = blockIdx.y;

    long long src, dst;
    if (is64) {
        const long long* e = (const long long*)edges_raw;
        src = e[2 * (long long)eid + 0];
        dst = e[2 * (long long)eid + 1];
    } else {
        const int* e = (const int*)edges_raw;
        src = e[2 * eid + 0];
        dst = e[2 * eid + 1];
    }

    const float4* xs = reinterpret_cast<const float4*>(x);
    float4 v = xs[((size_t)b * NNODES + (size_t)src) * ROW_F4 + c];
    float4* p = &g_agg[((size_t)b * NNODES + (size_t)dst) * ROW_F4 + c];
    asm volatile("red.global.add.v4.f32 [%0], {%1, %2, %3, %4};"
                 :: "l"(p), "f"(v.x), "f"(v.y), "f"(v.z), "f"(v.w)
                 : "memory");
}

// ---------------------------------------------------------------------------
// Kernel 3: fused dual-GEMM + bias + ReLU (lane = output-pair layout).
// Warp = 16-row tile. Half-warp h handles rows tileBase+2j+h (j=0..7);
// lane-in-half i owns outputs 4i..4i+3 as two f32x2 accumulators.
// Row loads (x/agg) are uniform per half-warp -> 2 lines per LDG.128.
// Weights register-resident per k-chunk of 8, amortized over 16 rows.
// ---------------------------------------------------------------------------
__global__ __launch_bounds__(128) void gemm_relu_kernel(
        const float* __restrict__ x,
        const float* __restrict__ Ws, const float* __restrict__ bs,
        const float* __restrict__ Wn, const float* __restrict__ bn,
        float* __restrict__ out) {
    __shared__ float sWs[DIM * DIM];   // [k][o]
    __shared__ float sWn[DIM * DIM];   // [k][o]
    __shared__ float sb[DIM];

    int tid = threadIdx.x;
    for (int idx = tid; idx < DIM * DIM; idx += 128) {
        int o = idx >> 6;
        int k = idx & 63;
        sWs[k * DIM + o] = Ws[idx];
        sWn[k * DIM + o] = Wn[idx];
    }
    if (tid < DIM) sb[tid] = bs[tid] + bn[tid];
    __syncthreads();

    int warp = tid >> 5;
    int lane = tid & 31;
    int h = lane >> 4;        // half-warp: which of the 2 concurrent rows
    int i = lane & 15;        // output group: owns outputs 4i..4i+3

    size_t tile = (size_t)blockIdx.x * 4 + warp;   // 16 rows per tile
    size_t rowbase = tile * 16;
    if (rowbase >= TOTAL_ROWS) return;

    // bias for this lane's 4 outputs
    float4 bv = *reinterpret_cast<const float4*>(&sb[4 * i]);
    unsigned long long bias0 = pack2(bv.x, bv.y);
    unsigned long long bias1 = pack2(bv.z, bv.w);

    unsigned long long acc[8][2];
#pragma unroll
    for (int j = 0; j < 8; j++) { acc[j][0] = bias0; acc[j][1] = bias1; }

    const float* aggf = reinterpret_cast<const float*>(g_agg);

#pragma unroll 1
    for (int c = 0; c < 8; c++) {
        int k0 = c * 8;

        // load this chunk's weights into registers: 8 k x 2 mats x 2 pairs
        unsigned long long wsv[8][2], wnv[8][2];
#pragma unroll
        for (int k = 0; k < 8; k++) {
            float4 w = *reinterpret_cast<const float4*>(&sWs[(k0 + k) * DIM + 4 * i]);
            wsv[k][0] = pack2(w.x, w.y);
            wsv[k][1] = pack2(w.z, w.w);
            float4 u = *reinterpret_cast<const float4*>(&sWn[(k0 + k) * DIM + 4 * i]);
            wnv[k][0] = pack2(u.x, u.y);
            wnv[k][1] = pack2(u.z, u.w);
        }

#pragma unroll
        for (int j = 0; j < 8; j++) {
            size_t row = rowbase + 2 * (size_t)j + h;
            const float4* xr = reinterpret_cast<const float4*>(x + row * DIM + k0);
            const float4* ar = reinterpret_cast<const float4*>(aggf + row * DIM + k0);
            float4 xa = xr[0];
            float4 xb4 = xr[1];
            float4 aa = ar[0];
            float4 ab4 = ar[1];
            float xsv[8] = {xa.x, xa.y, xa.z, xa.w, xb4.x, xb4.y, xb4.z, xb4.w};
            float asv[8] = {aa.x, aa.y, aa.z, aa.w, ab4.x, ab4.y, ab4.z, ab4.w};
#pragma unroll
            for (int k = 0; k < 8; k++) {
                unsigned long long xp = pack2(xsv[k], xsv[k]);
                unsigned long long ap = pack2(asv[k], asv[k]);
                acc[j][0] = fma2(xp, wsv[k][0], acc[j][0]);
                acc[j][0] = fma2(ap, wnv[k][0], acc[j][0]);
                acc[j][1] = fma2(xp, wsv[k][1], acc[j][1]);
                acc[j][1] = fma2(ap, wnv[k][1], acc[j][1]);
            }
        }
    }

    // epilogue: relu + coalesced STG.128
#pragma unroll
    for (int j = 0; j < 8; j++) {
        size_t row = rowbase + 2 * (size_t)j + h;
        float l0, h0, l1, h1;
        unpack2(acc[j][0], l0, h0);
        unpack2(acc[j][1], l1, h1);
        float4 r;
        r.x = fmaxf(l0, 0.f);
        r.y = fmaxf(h0, 0.f);
        r.z = fmaxf(l1, 0.f);
        r.w = fmaxf(h1, 0.f);
        *reinterpret_cast<float4*>(out + row * DIM + 4 * i) = r;
    }
}

// ---------------------------------------------------------------------------
// Launch
// ---------------------------------------------------------------------------
extern "C" void kernel_launch(void* const* d_in, const int* in_sizes, int n_in,
                              void* d_out, int out_size) {
    const float* x = (const float*)d_in[0];
    const void* edges = d_in[1];
    const float* Ws = (const float*)d_in[2];
    const float* bs = (const float*)d_in[3];
    const float* Wn = (const float*)d_in[4];
    const float* bn = (const float*)d_in[5];
    float* out = (float*)d_out;

    int nwords = in_sizes[1];
    int max_edges = nwords / 2;

    detect_dtype_kernel<<<1, 256>>>((const int*)edges, nwords);
    zero_agg_kernel<<<2048, 256>>>();

    {
        size_t threads_needed = (size_t)max_edges * 16;
        int blocks_x = (int)((threads_needed + 255) / 256);
        dim3 grid(blocks_x, BATCH, 1);
        scatter_kernel<<<grid, 256>>>(x, edges, nwords);
    }

    // gemm: 16 rows per warp-tile, 4 warps per block -> 64 rows per block
    int gblocks = (int)((TOTAL_ROWS + 63) / 64);   // 6250
    gemm_relu_kernel<<<gblocks, 128>>>(x, Ws, bs, Wn, bn, out);
}

// round 6
// speedup vs baseline: 1.3355x; 1.3355x over previous
#include <cuda_runtime.h>
#include <cstdint>

#define BATCH 8
#define NNODES 50000
#define DIM 64
#define ROW_F4 16
#define TOTAL_ROWS ((size_t)BATCH * NNODES)   // 400000

__device__ float4 g_agg[TOTAL_ROWS * ROW_F4];   // 102.4 MB scratch, 16B-aligned
__device__ int g_is64;

// ---------------------------------------------------------------------------
// packed f32x2 helpers
// ---------------------------------------------------------------------------
__device__ __forceinline__ unsigned long long pack2(float a, float b) {
    unsigned long long r;
    asm("mov.b64 %0, {%1, %2};" : "=l"(r) : "f"(a), "f"(b));
    return r;
}
__device__ __forceinline__ unsigned long long fma2(unsigned long long a,
                                                   unsigned long long b,
                                                   unsigned long long c) {
    unsigned long long d;
    asm("fma.rn.f32x2 %0, %1, %2, %3;" : "=l"(d) : "l"(a), "l"(b), "l"(c));
    return d;
}
__device__ __forceinline__ void unpack2(unsigned long long v, float& lo, float& hi) {
    asm("mov.b64 {%0, %1}, %2;" : "=f"(lo), "=f"(hi) : "l"(v));
}

// ---------------------------------------------------------------------------
// Kernel 0: detect edge_index dtype (int64 LE => odd 32-bit words all zero).
// ---------------------------------------------------------------------------
__global__ void detect_dtype_kernel(const int* __restrict__ w, int nwords) {
    __shared__ int any_nonzero;
    if (threadIdx.x == 0) any_nonzero = 0;
    __syncthreads();
    int limit = nwords / 2;
    if (limit > 16384) limit = 16384;
    for (int i = threadIdx.x; i < limit; i += blockDim.x) {
        if (w[2 * i + 1] != 0) any_nonzero = 1;
    }
    __syncthreads();
    if (threadIdx.x == 0) g_is64 = (any_nonzero == 0) ? 1 : 0;
}

// ---------------------------------------------------------------------------
// Kernel 1: zero agg
// ---------------------------------------------------------------------------
__global__ void zero_agg_kernel() {
    const size_t total4 = TOTAL_ROWS * ROW_F4;
    float4 z = make_float4(0.f, 0.f, 0.f, 0.f);
    for (size_t i = (size_t)blockIdx.x * blockDim.x + threadIdx.x;
         i < total4;
         i += (size_t)gridDim.x * blockDim.x) {
        g_agg[i] = z;
    }
}

// ---------------------------------------------------------------------------
// Kernel 2: batch-phased edge scatter (unchanged; near L2 atomic cap)
// ---------------------------------------------------------------------------
__global__ void scatter_kernel(const float* __restrict__ x,
                               const void* __restrict__ edges_raw,
                               int nwords) {
    int is64 = g_is64;
    int num_edges;
    if (is64) {
        num_edges = (nwords >= 3000000) ? (nwords >> 2) : (nwords >> 1);
    } else {
        num_edges = nwords >> 1;
    }

    size_t gtid = (size_t)blockIdx.x * blockDim.x + threadIdx.x;
    int eid = (int)(gtid >> 4);
    int c = (int)(gtid & 15);
    if (eid >= num_edges) return;

    int b = blockIdx.y;

    long long src, dst;
    if (is64) {
        const long long* e = (const long long*)edges_raw;
        src = e[2 * (long long)eid + 0];
        dst = e[2 * (long long)eid + 1];
    } else {
        const int* e = (const int*)edges_raw;
        src = e[2 * eid + 0];
        dst = e[2 * eid + 1];
    }

    const float4* xs = reinterpret_cast<const float4*>(x);
    float4 v = xs[((size_t)b * NNODES + (size_t)src) * ROW_F4 + c];
    float4* p = &g_agg[((size_t)b * NNODES + (size_t)dst) * ROW_F4 + c];
    asm volatile("red.global.add.v4.f32 [%0], {%1, %2, %3, %4};"
                 :: "l"(p), "f"(v.x), "f"(v.y), "f"(v.z), "f"(v.w)
                 : "memory");
}

// ---------------------------------------------------------------------------
// Kernel 3: fused dual-GEMM + bias + ReLU, smem-staged rows.
// Block = 256 threads (8 warps), 128 rows. Staging: coalesced LDG.128 of the
// x/agg row tiles into smem. Compute: warp w owns rows [16w,16w+16);
// half-warp h = one row of the pair, lane-in-half i owns outputs 4i..4i+3.
// Row data read via broadcast LDS (uniform per half-warp, conflict-free);
// weights register-cached per 4-k chunk (32 regs).
// ---------------------------------------------------------------------------
#define WSTRIDE 68        // padded [k][o] stride (16B-aligned, low STS conflicts)
#define SX_OFF 0                         // 128*64 floats
#define SA_OFF (128 * 64)                // 128*64 floats
#define SWS_OFF (2 * 128 * 64)           // 64*68
#define SWN_OFF (SWS_OFF + 64 * WSTRIDE)
#define SB_OFF (SWN_OFF + 64 * WSTRIDE)
#define SMEM_FLOATS (SB_OFF + 64)

__global__ __launch_bounds__(256) void gemm_relu_kernel(
        const float* __restrict__ x,
        const float* __restrict__ Ws, const float* __restrict__ bs,
        const float* __restrict__ Wn, const float* __restrict__ bn,
        float* __restrict__ out) {
    extern __shared__ float sm[];
    float* sX = sm + SX_OFF;
    float* sA = sm + SA_OFF;
    float* sWs = sm + SWS_OFF;
    float* sWn = sm + SWN_OFF;
    float* sb = sm + SB_OFF;

    int tid = threadIdx.x;
    size_t rowbase = (size_t)blockIdx.x * 128;

    // --- stage rows: 128 rows x 16 float4, coalesced ---
    {
        const float4* xg = reinterpret_cast<const float4*>(x + rowbase * DIM);
        const float4* ag = &g_agg[rowbase * ROW_F4];
        float4* sx4 = reinterpret_cast<float4*>(sX);
        float4* sa4 = reinterpret_cast<float4*>(sA);
#pragma unroll
        for (int t = 0; t < 8; t++) {
            int idx = tid + t * 256;       // 0..2047
            sx4[idx] = xg[idx];
            sa4[idx] = ag[idx];
        }
    }
    // --- stage weights transposed [k][o], bias ---
    for (int idx = tid; idx < DIM * DIM; idx += 256) {
        int o = idx >> 6;
        int k = idx & 63;
        sWs[k * WSTRIDE + o] = Ws[idx];
        sWn[k * WSTRIDE + o] = Wn[idx];
    }
    if (tid < DIM) sb[tid] = bs[tid] + bn[tid];
    __syncthreads();

    int warp = tid >> 5;
    int lane = tid & 31;
    int h = lane >> 4;        // row parity within pair
    int i = lane & 15;        // owns outputs 4i..4i+3

    // bias init
    unsigned long long bias0 = pack2(sb[4 * i], sb[4 * i + 1]);
    unsigned long long bias1 = pack2(sb[4 * i + 2], sb[4 * i + 3]);
    unsigned long long acc[8][2];
#pragma unroll
    for (int j = 0; j < 8; j++) { acc[j][0] = bias0; acc[j][1] = bias1; }

    int row0 = warp * 16 + h;   // local row for j=0

#pragma unroll 1
    for (int c = 0; c < 16; c++) {
        int k0 = c * 4;

        // register-cache this chunk's weights (4 k x 2 mats x 2 f32x2)
        unsigned long long wsv[4][2], wnv[4][2];
#pragma unroll
        for (int k = 0; k < 4; k++) {
            float4 w = *reinterpret_cast<const float4*>(&sWs[(k0 + k) * WSTRIDE + 4 * i]);
            wsv[k][0] = pack2(w.x, w.y);
            wsv[k][1] = pack2(w.z, w.w);
            float4 u = *reinterpret_cast<const float4*>(&sWn[(k0 + k) * WSTRIDE + 4 * i]);
            wnv[k][0] = pack2(u.x, u.y);
            wnv[k][1] = pack2(u.z, u.w);
        }

#pragma unroll
        for (int j = 0; j < 8; j++) {
            int r = row0 + 2 * j;
            float4 xv = *reinterpret_cast<const float4*>(&sX[r * DIM + k0]);
            float4 av = *reinterpret_cast<const float4*>(&sA[r * DIM + k0]);
            float xe[4] = {xv.x, xv.y, xv.z, xv.w};
            float ae[4] = {av.x, av.y, av.z, av.w};
#pragma unroll
            for (int k = 0; k < 4; k++) {
                unsigned long long xp = pack2(xe[k], xe[k]);
                unsigned long long ap = pack2(ae[k], ae[k]);
                acc[j][0] = fma2(xp, wsv[k][0], acc[j][0]);
                acc[j][0] = fma2(ap, wnv[k][0], acc[j][0]);
                acc[j][1] = fma2(xp, wsv[k][1], acc[j][1]);
                acc[j][1] = fma2(ap, wnv[k][1], acc[j][1]);
            }
        }
    }

    // epilogue: relu + STG.128 (contiguous 256B per half-warp)
#pragma unroll
    for (int j = 0; j < 8; j++) {
        size_t row = rowbase + (size_t)(row0 + 2 * j);
        float l0, h0, l1, h1;
        unpack2(acc[j][0], l0, h0);
        unpack2(acc[j][1], l1, h1);
        float4 r;
        r.x = fmaxf(l0, 0.f);
        r.y = fmaxf(h0, 0.f);
        r.z = fmaxf(l1, 0.f);
        r.w = fmaxf(h1, 0.f);
        *reinterpret_cast<float4*>(out + row * DIM + 4 * i) = r;
    }
}

// ---------------------------------------------------------------------------
// Launch
// ---------------------------------------------------------------------------
extern "C" void kernel_launch(void* const* d_in, const int* in_sizes, int n_in,
                              void* d_out, int out_size) {
    const float* x = (const float*)d_in[0];
    const void* edges = d_in[1];
    const float* Ws = (const float*)d_in[2];
    const float* bs = (const float*)d_in[3];
    const float* Wn = (const float*)d_in[4];
    const float* bn = (const float*)d_in[5];
    float* out = (float*)d_out;

    int nwords = in_sizes[1];
    int max_edges = nwords / 2;

    detect_dtype_kernel<<<1, 256>>>((const int*)edges, nwords);
    zero_agg_kernel<<<2048, 256>>>();

    {
        size_t threads_needed = (size_t)max_edges * 16;
        int blocks_x = (int)((threads_needed + 255) / 256);
        dim3 grid(blocks_x, BATCH, 1);
        scatter_kernel<<<grid, 256>>>(x, edges, nwords);
    }

    // gemm: 128 rows per block, dynamic smem ~98.5 KB
    int smem_bytes = SMEM_FLOATS * (int)sizeof(float);
    cudaFuncSetAttribute(gemm_relu_kernel,
                         cudaFuncAttributeMaxDynamicSharedMemorySize, smem_bytes);
    int gblocks = (int)(TOTAL_ROWS / 128);   // 3125, exact
    gemm_relu_kernel<<<gblocks, 256, smem_bytes>>>(x, Ws, bs, Wn, bn, out);
}